// round 2
// baseline (speedup 1.0000x reference)
#include <cuda_runtime.h>
#include <cstdint>

typedef unsigned long long u64;
typedef unsigned int u32;

// ---- packed fp32x2 helpers (sm_103a) ----
__device__ __forceinline__ u64 ffma2(u64 a, u64 b, u64 c) {
    u64 d; asm("fma.rn.f32x2 %0, %1, %2, %3;" : "=l"(d) : "l"(a), "l"(b), "l"(c)); return d;
}
__device__ __forceinline__ u64 pack2(float x, float y) {
    u64 r; asm("mov.b64 %0, {%1, %2};" : "=l"(r) : "f"(x), "f"(y)); return r;
}
__device__ __forceinline__ float2 unpack2(u64 v) {
    float2 r; asm("mov.b64 {%0, %1}, %2;" : "=f"(r.x), "=f"(r.y) : "l"(v)); return r;
}
__device__ __forceinline__ float clip1(float v) { return fminf(fmaxf(v, -1.0f), 1.0f); }
__device__ __forceinline__ u64 shflx16(u64 v) {
    u32 lo = (u32)v, hi = (u32)(v >> 32);
    lo = __shfl_xor_sync(0xffffffffu, lo, 16);
    hi = __shfl_xor_sync(0xffffffffu, hi, 16);
    return ((u64)hi << 32) | (u64)lo;
}

constexpr int NWARP    = 8;
constexpr int NTHREADS = NWARP * 32;
constexpr int ROWS_W   = 16;        // rows per warp (2 lanes per row)
constexpr int INSTRIDE = 390;       // floats per staged row (385 + pad; 390%32=6 -> conflict-free)
constexpr int VSTRIDE  = 38;        // v scratch stride

constexpr int SW1_N = 27 * 8;       // u64 weight pairs
constexpr int SW2_N = 4 * 8;
constexpr int E1T_N = 19 * 16;
constexpr int E2T_N = 8 * 16;
constexpr int IN_N  = NWARP * ROWS_W * INSTRIDE;   // floats
constexpr int VB_N  = NWARP * ROWS_W * VSTRIDE;    // floats
constexpr size_t SMEM_BYTES =
    (size_t)(SW1_N + SW2_N + E1T_N + E2T_N) * 8 + (size_t)(IN_N + VB_N) * 4;

__global__ __launch_bounds__(NTHREADS, 1)
void lila_kernel(const float* __restrict__ inp,
                 const float* __restrict__ W1, const float* __restrict__ b1,
                 const float* __restrict__ W2, const float* __restrict__ b2,
                 const float* __restrict__ W3, const float* __restrict__ b3,
                 const float* __restrict__ E1, const float* __restrict__ c1,
                 const float* __restrict__ E2, const float* __restrict__ c2,
                 const float* __restrict__ E3, const float* __restrict__ c3,
                 float* __restrict__ out, int B)
{
    extern __shared__ __align__(16) char smem_raw[];
    u64*   SW1 = reinterpret_cast<u64*>(smem_raw);
    u64*   SW2 = SW1 + SW1_N;
    u64*   E1T = SW2 + SW2_N;
    u64*   E2T = E1T + E1T_N;
    float* IN  = reinterpret_cast<float*>(E2T + E2T_N);
    float* VB  = IN + IN_N;

    const int tid  = threadIdx.x;
    const int lane = tid & 31;
    const int warp = tid >> 5;
    const int h    = lane >> 4;     // output half: 0 -> o 0..3 / 0..7 ; 1 -> 4..7 / 8..15
    const int r    = lane & 15;     // row index within warp

    // ---- stage packed weights (block-wide, once) ----
    for (int i = tid; i < SW1_N; i += NTHREADS) {
        int fp = i >> 3, o = i & 7;
        SW1[i] = pack2(W1[(2 * fp) * 8 + o], W1[(2 * fp + 1) * 8 + o]);
    }
    for (int i = tid; i < SW2_N; i += NTHREADS) {
        int fp = i >> 3, o = i & 7;
        SW2[i] = pack2(W2[(2 * fp) * 8 + o], W2[(2 * fp + 1) * 8 + o]);
    }
    for (int i = tid; i < E1T_N; i += NTHREADS) {
        int fp = i >> 4, o = i & 15;
        E1T[i] = (fp < 18) ? pack2(E1[(2 * fp) * 16 + o], E1[(2 * fp + 1) * 16 + o])
                           : pack2(E1[36 * 16 + o], 0.0f);
    }
    for (int i = tid; i < E2T_N; i += NTHREADS) {
        int fp = i >> 4, o = i & 15;
        E2T[i] = pack2(E2[(2 * fp) * 16 + o], E2[(2 * fp + 1) * 16 + o]);
    }

    // ---- per-lane constants ----
    u64 binit1[4], binit2[4], cinit1[8], cinit2[8], w3p[2], e3p[4];
#pragma unroll
    for (int j = 0; j < 4; j++) {
        binit1[j] = pack2(__ldg(b1 + 4 * h + j), 0.0f);
        binit2[j] = pack2(__ldg(b2 + 4 * h + j), 0.0f);
    }
#pragma unroll
    for (int j = 0; j < 8; j++) {
        cinit1[j] = pack2(__ldg(c1 + 8 * h + j), 0.0f);
        cinit2[j] = pack2(__ldg(c2 + 8 * h + j), 0.0f);
    }
    w3p[0] = pack2(__ldg(W3 + 4 * h + 0), __ldg(W3 + 4 * h + 1));
    w3p[1] = pack2(__ldg(W3 + 4 * h + 2), __ldg(W3 + 4 * h + 3));
#pragma unroll
    for (int j = 0; j < 4; j++)
        e3p[j] = pack2(__ldg(E3 + 8 * h + 2 * j), __ldg(E3 + 8 * h + 2 * j + 1));
    const float b3s = __ldg(b3);
    const float c3s = __ldg(c3);

    __syncthreads();

    float* warp_in = IN + warp * (ROWS_W * INSTRIDE);
    float* warp_vb = VB + warp * (ROWS_W * VSTRIDE);
    float* lane_in = warp_in + r * INSTRIDE;
    float* lane_vb = warp_vb + r * VSTRIDE;

    const int wg      = blockIdx.x * NWARP + warp;
    const int rowstep = gridDim.x * NWARP * ROWS_W;

    for (int rb = wg * ROWS_W; rb < B; rb += rowstep) {
        __syncwarp();

        // ---- stage 16 rows x 385 floats (coalesced LDG.32) ----
#pragma unroll 1
        for (int rr = 0; rr < ROWS_W; rr++) {
            int row = rb + rr;
            const float* src = inp + (size_t)row * 385;
            float* dst = warp_in + rr * INSTRIDE;
            bool ok = (row < B);
#pragma unroll
            for (int k = 0; k < 13; k++) {
                int f = lane + 32 * k;
                if (f < 385) dst[f] = ok ? __ldg(src + f) : 0.0f;
            }
            if (lane < 5) dst[385 + lane] = 0.0f;   // pad (incl. head pair partner of f=384)
        }
        __syncwarp();

        // ---- per-patch network: 54->8->8->1 ----
#pragma unroll 1
        for (int p = 0; p < 36; p++) {
            int x = p / 6, y = p - 6 * (p / 6);
            const float* base = lane_in + x * 48 + y * 6;

            u64 a0 = binit1[0], a1 = binit1[1], a2 = binit1[2], a3 = binit1[3];
#pragma unroll
            for (int c = 0; c < 9; c++) {
                int ox = c / 3, oy = c - 3 * (c / 3);
                const float* cp = base + ox * 48 + oy * 6;
                u64 i0 = *reinterpret_cast<const u64*>(cp + 0);
                u64 i1 = *reinterpret_cast<const u64*>(cp + 2);
                u64 i2 = *reinterpret_cast<const u64*>(cp + 4);
#pragma unroll
                for (int j = 0; j < 3; j++) {
                    u64 iv = (j == 0) ? i0 : (j == 1) ? i1 : i2;
                    const u64* wrow = SW1 + (3 * c + j) * 8 + 4 * h;
                    ulonglong2 wlo = *reinterpret_cast<const ulonglong2*>(wrow);
                    ulonglong2 whi = *reinterpret_cast<const ulonglong2*>(wrow + 2);
                    a0 = ffma2(iv, wlo.x, a0);
                    a1 = ffma2(iv, wlo.y, a1);
                    a2 = ffma2(iv, whi.x, a2);
                    a3 = ffma2(iv, whi.y, a3);
                }
            }
            float2 f0 = unpack2(a0), f1 = unpack2(a1), f2 = unpack2(a2), f3 = unpack2(a3);
            float h0 = clip1(f0.x + f0.y), h1v = clip1(f1.x + f1.y);
            float h2v = clip1(f2.x + f2.y), h3v = clip1(f3.x + f3.y);

            // exchange -> each lane holds all 8 h1 values as 4 packed pairs (o order)
            u64 m0 = pack2(h0, h1v), m1 = pack2(h2v, h3v);
            u64 p0 = shflx16(m0), p1 = shflx16(m1);
            u64 x0 = h ? p0 : m0, x1 = h ? p1 : m1;
            u64 x2 = h ? m0 : p0, x3 = h ? m1 : p1;

            // layer 2: 8 -> 8 (this lane's 4 outputs)
            u64 c0 = binit2[0], c1a = binit2[1], c2a = binit2[2], c3a = binit2[3];
#pragma unroll
            for (int fp = 0; fp < 4; fp++) {
                u64 iv = (fp == 0) ? x0 : (fp == 1) ? x1 : (fp == 2) ? x2 : x3;
                const u64* wrow = SW2 + fp * 8 + 4 * h;
                ulonglong2 wlo = *reinterpret_cast<const ulonglong2*>(wrow);
                ulonglong2 whi = *reinterpret_cast<const ulonglong2*>(wrow + 2);
                c0  = ffma2(iv, wlo.x, c0);
                c1a = ffma2(iv, wlo.y, c1a);
                c2a = ffma2(iv, whi.x, c2a);
                c3a = ffma2(iv, whi.y, c3a);
            }
            float2 g0 = unpack2(c0), g1 = unpack2(c1a), g2 = unpack2(c2a), g3 = unpack2(c3a);
            u64 n0 = pack2(clip1(g0.x + g0.y), clip1(g1.x + g1.y));
            u64 n1 = pack2(clip1(g2.x + g2.y), clip1(g3.x + g3.y));

            // layer 3: dot8 -> v
            u64 s = ffma2(n0, w3p[0], ffma2(n1, w3p[1], 0ull));
            float2 sf = unpack2(s);
            float part = sf.x + sf.y;
            float tot = part + __shfl_xor_sync(0xffffffffu, part, 16);
            if (h == 0) lane_vb[p] = clip1(tot + b3s);
        }
        __syncwarp();

        // ---- head: vision[37] -> 16 -> 16 -> 1 ----
        u64 g[8];
#pragma unroll
        for (int j = 0; j < 8; j++) g[j] = cinit1[j];
#pragma unroll
        for (int fp = 0; fp < 19; fp++) {
            u64 iv = (fp < 18) ? *reinterpret_cast<const u64*>(lane_vb + 2 * fp)
                               : *reinterpret_cast<const u64*>(lane_in + 384);
            const u64* wrow = E1T + fp * 16 + 8 * h;
#pragma unroll
            for (int t = 0; t < 4; t++) {
                ulonglong2 wv = *reinterpret_cast<const ulonglong2*>(wrow + 2 * t);
                g[2 * t + 0] = ffma2(iv, wv.x, g[2 * t + 0]);
                g[2 * t + 1] = ffma2(iv, wv.y, g[2 * t + 1]);
            }
        }
        float gv[8];
#pragma unroll
        for (int j = 0; j < 8; j++) {
            float2 f = unpack2(g[j]);
            gv[j] = clip1(f.x + f.y);
        }
        u64 q0 = pack2(gv[0], gv[1]), q1 = pack2(gv[2], gv[3]);
        u64 q2 = pack2(gv[4], gv[5]), q3 = pack2(gv[6], gv[7]);
        u64 s0 = shflx16(q0), s1 = shflx16(q1), s2 = shflx16(q2), s3 = shflx16(q3);
        u64 z[8];
        z[0] = h ? s0 : q0; z[1] = h ? s1 : q1; z[2] = h ? s2 : q2; z[3] = h ? s3 : q3;
        z[4] = h ? q0 : s0; z[5] = h ? q1 : s1; z[6] = h ? q2 : s2; z[7] = h ? q3 : s3;

        u64 d[8];
#pragma unroll
        for (int j = 0; j < 8; j++) d[j] = cinit2[j];
#pragma unroll
        for (int fp = 0; fp < 8; fp++) {
            const u64* wrow = E2T + fp * 16 + 8 * h;
#pragma unroll
            for (int t = 0; t < 4; t++) {
                ulonglong2 wv = *reinterpret_cast<const ulonglong2*>(wrow + 2 * t);
                d[2 * t + 0] = ffma2(z[fp], wv.x, d[2 * t + 0]);
                d[2 * t + 1] = ffma2(z[fp], wv.y, d[2 * t + 1]);
            }
        }
        float dv[8];
#pragma unroll
        for (int j = 0; j < 8; j++) {
            float2 f = unpack2(d[j]);
            dv[j] = clip1(f.x + f.y);
        }
        u64 r0 = pack2(dv[0], dv[1]), r1 = pack2(dv[2], dv[3]);
        u64 r2 = pack2(dv[4], dv[5]), r3 = pack2(dv[6], dv[7]);
        u64 sa = ffma2(r0, e3p[0], ffma2(r2, e3p[2], 0ull));
        u64 sb = ffma2(r1, e3p[1], ffma2(r3, e3p[3], 0ull));
        float2 fa = unpack2(sa), fb = unpack2(sb);
        float part = (fa.x + fa.y) + (fb.x + fb.y);
        float tot = part + __shfl_xor_sync(0xffffffffu, part, 16);
        int row = rb + r;
        if (h == 0 && row < B) out[row] = clip1(tot + c3s);
    }
}

extern "C" void kernel_launch(void* const* d_in, const int* in_sizes, int n_in,
                              void* d_out, int out_size)
{
    const float* inp = (const float*)d_in[0];
    const float* W1  = (const float*)d_in[1];
    const float* b1  = (const float*)d_in[2];
    const float* W2  = (const float*)d_in[3];
    const float* b2  = (const float*)d_in[4];
    const float* W3  = (const float*)d_in[5];
    const float* b3  = (const float*)d_in[6];
    const float* E1  = (const float*)d_in[7];
    const float* c1  = (const float*)d_in[8];
    const float* E2  = (const float*)d_in[9];
    const float* c2  = (const float*)d_in[10];
    const float* E3  = (const float*)d_in[11];
    const float* c3  = (const float*)d_in[12];

    int B = in_sizes[0] / 385;

    cudaFuncSetAttribute(lila_kernel, cudaFuncAttributeMaxDynamicSharedMemorySize,
                         (int)SMEM_BYTES);

    lila_kernel<<<148, NTHREADS, SMEM_BYTES>>>(inp, W1, b1, W2, b2, W3, b3,
                                               E1, c1, E2, c2, E3, c3,
                                               (float*)d_out, B);
}

// round 3
// speedup vs baseline: 1.9837x; 1.9837x over previous
#include <cuda_runtime.h>
#include <cstdint>

typedef unsigned long long u64;
typedef unsigned int u32;

__device__ __forceinline__ u64 ffma2(u64 a, u64 b, u64 c) {
    u64 d; asm("fma.rn.f32x2 %0, %1, %2, %3;" : "=l"(d) : "l"(a), "l"(b), "l"(c)); return d;
}
__device__ __forceinline__ u64 pack2(float x, float y) {
    u64 r; asm("mov.b64 %0, {%1, %2};" : "=l"(r) : "f"(x), "f"(y)); return r;
}
__device__ __forceinline__ float2 unpack2(u64 v) {
    float2 r; asm("mov.b64 {%0, %1}, %2;" : "=f"(r.x), "=f"(r.y) : "l"(v)); return r;
}
__device__ __forceinline__ float clip1(float v) { return fminf(fmaxf(v, -1.0f), 1.0f); }
__device__ __forceinline__ u64 shfl64(u64 v, int src) {
    u32 lo = (u32)v, hi = (u32)(v >> 32);
    lo = __shfl_sync(0xffffffffu, lo, src);
    hi = __shfl_sync(0xffffffffu, hi, src);
    return ((u64)hi << 32) | (u64)lo;
}

constexpr int NWARP    = 8;
constexpr int NTHREADS = 256;
constexpr int ROWS_W   = 8;          // rows per warp per iteration
constexpr int INSTRIDE = 386;        // floats per staged row (even; 386%32=2)
constexpr int VSTRIDE  = 38;

constexpr int SW1_N = 27 * 8;        // u64: [fp][o]
constexpr int SW2_N = 4 * 8;         // u64: [fp][o]
constexpr int E1T_N = 19 * 16;       // u64: [fp][o]
constexpr int E2T_N = 8 * 16;        // u64: [fp][o]
constexpr int WU_N  = SW1_N + SW2_N + E1T_N + E2T_N;      // 680 u64
constexpr int IN_N  = NWARP * ROWS_W * INSTRIDE;          // floats
constexpr int VB_N  = NWARP * ROWS_W * VSTRIDE;           // floats
constexpr size_t SMEM_BYTES = (size_t)WU_N * 8 + (size_t)(IN_N + VB_N) * 4;

__global__ __launch_bounds__(NTHREADS, 2)
void lila_kernel(const float* __restrict__ inp,
                 const float* __restrict__ W1, const float* __restrict__ b1,
                 const float* __restrict__ W2, const float* __restrict__ b2,
                 const float* __restrict__ W3, const float* __restrict__ b3,
                 const float* __restrict__ E1, const float* __restrict__ c1,
                 const float* __restrict__ E2, const float* __restrict__ c2,
                 const float* __restrict__ E3, const float* __restrict__ c3,
                 float* __restrict__ out, int B)
{
    extern __shared__ __align__(16) char smem_raw[];
    u64*   SW1 = reinterpret_cast<u64*>(smem_raw);
    u64*   SW2 = SW1 + SW1_N;
    u64*   E1T = SW2 + SW2_N;
    u64*   E2T = E1T + E1T_N;
    float* IN  = reinterpret_cast<float*>(E2T + E2T_N);
    float* VB  = IN + IN_N;

    const int tid  = threadIdx.x;
    const int lane = tid & 31;
    const int warp = tid >> 5;

    // ---- stage weights into SMEM (u64 pairs along the feature axis) ----
    for (int i = tid; i < SW1_N; i += NTHREADS) {
        int fp = i >> 3, o = i & 7;
        SW1[i] = pack2(W1[(2 * fp) * 8 + o], W1[(2 * fp + 1) * 8 + o]);
    }
    for (int i = tid; i < SW2_N; i += NTHREADS) {
        int fp = i >> 3, o = i & 7;
        SW2[i] = pack2(W2[(2 * fp) * 8 + o], W2[(2 * fp + 1) * 8 + o]);
    }
    for (int i = tid; i < E1T_N; i += NTHREADS) {
        int fp = i >> 4, o = i & 15;
        E1T[i] = (fp < 18) ? pack2(E1[(2 * fp) * 16 + o], E1[(2 * fp + 1) * 16 + o])
                           : pack2(E1[36 * 16 + o], 0.0f);
    }
    for (int i = tid; i < E2T_N; i += NTHREADS) {
        int fp = i >> 4, o = i & 15;
        E2T[i] = pack2(E2[(2 * fp) * 16 + o], E2[(2 * fp + 1) * 16 + o]);
    }

    // ---- small per-lane constants ----
    float b1f[8], b2f[8];
#pragma unroll
    for (int o = 0; o < 8; o++) { b1f[o] = __ldg(b1 + o); b2f[o] = __ldg(b2 + o); }
    u64 w3p[4];
#pragma unroll
    for (int q = 0; q < 4; q++) w3p[q] = pack2(__ldg(W3 + 2 * q), __ldg(W3 + 2 * q + 1));
    const float b3s = __ldg(b3);
    const float c3s = __ldg(c3);

    // head lane mapping: r = lane&7 (row), oq = lane>>3 (out quad)
    const int hr  = lane & 7;
    const int hoq = lane >> 3;
    float c1f[4], c2f[4];
#pragma unroll
    for (int k = 0; k < 4; k++) {
        c1f[k] = __ldg(c1 + 4 * hoq + k);
        c2f[k] = __ldg(c2 + 4 * hoq + k);
    }
    u64 e3p0 = pack2(__ldg(E3 + 4 * hoq + 0), __ldg(E3 + 4 * hoq + 1));
    u64 e3p1 = pack2(__ldg(E3 + 4 * hoq + 2), __ldg(E3 + 4 * hoq + 3));

    __syncthreads();

    float* warp_in = IN + warp * (ROWS_W * INSTRIDE);
    float* warp_vb = VB + warp * (ROWS_W * VSTRIDE);

    const ulonglong2* SW1v = reinterpret_cast<const ulonglong2*>(SW1);
    const ulonglong2* SW2v = reinterpret_cast<const ulonglong2*>(SW2);
    const ulonglong2* E1Tv = reinterpret_cast<const ulonglong2*>(E1T);
    const ulonglong2* E2Tv = reinterpret_cast<const ulonglong2*>(E2T);

    const int wg      = blockIdx.x * NWARP + warp;
    const int rowstep = gridDim.x * NWARP * ROWS_W;

    for (int rb = wg * ROWS_W; rb < B; rb += rowstep) {
        __syncwarp();

        // ---- stage 8 rows ----
#pragma unroll
        for (int rr = 0; rr < ROWS_W; rr++) {
            int row = rb + rr;
            float* dst = warp_in + rr * INSTRIDE;
            if (row < B) {
                const float* src = inp + (size_t)row * 385;
#pragma unroll
                for (int k = 0; k < 13; k++) {
                    int f = lane + 32 * k;
                    if (f < 385) dst[f] = __ldg(src + f);
                }
            } else {
#pragma unroll
                for (int k = 0; k < 13; k++) {
                    int f = lane + 32 * k;
                    if (f < 385) dst[f] = 0.0f;
                }
            }
        }
        if (lane < ROWS_W) {
            int row = rb + lane;
            warp_vb[lane * VSTRIDE + 36] = (row < B) ? __ldg(inp + (size_t)row * 385 + 384) : 0.0f;
            warp_vb[lane * VSTRIDE + 37] = 0.0f;
        }
        __syncwarp();

        // ---- 288 patch-tasks = 3 loops x (32 lanes x 3 patches) ----
#pragma unroll 1
        for (int li = 0; li < 3; li++) {
            int t0 = li * 96 + lane;
            int t1 = t0 + 32, t2 = t0 + 64;
            int r0 = t0 / 36, p0 = t0 - 36 * r0;
            int r1 = t1 / 36, p1 = t1 - 36 * r1;
            int r2 = t2 / 36, p2 = t2 - 36 * r2;
            const float* base0 = warp_in + r0 * INSTRIDE + (p0 / 6) * 48 + (p0 % 6) * 6;
            const float* base1 = warp_in + r1 * INSTRIDE + (p1 / 6) * 48 + (p1 % 6) * 6;
            const float* base2 = warp_in + r2 * INSTRIDE + (p2 / 6) * 48 + (p2 % 6) * 6;

            u64 acc[3][8];
#pragma unroll
            for (int t = 0; t < 3; t++)
#pragma unroll
                for (int o = 0; o < 8; o++) acc[t][o] = 0ull;

            // layer 1: 27 feature-pairs
#pragma unroll
            for (int c = 0; c < 9; c++) {
                const int off = (c / 3) * 48 + (c % 3) * 6;
#pragma unroll
                for (int j = 0; j < 3; j++) {
                    const int fp = 3 * c + j;
                    u64 i0 = *reinterpret_cast<const u64*>(base0 + off + 2 * j);
                    u64 i1 = *reinterpret_cast<const u64*>(base1 + off + 2 * j);
                    u64 i2 = *reinterpret_cast<const u64*>(base2 + off + 2 * j);
#pragma unroll
                    for (int q = 0; q < 4; q++) {
                        ulonglong2 wv = SW1v[fp * 4 + q];
                        acc[0][2 * q]     = ffma2(i0, wv.x, acc[0][2 * q]);
                        acc[0][2 * q + 1] = ffma2(i0, wv.y, acc[0][2 * q + 1]);
                        acc[1][2 * q]     = ffma2(i1, wv.x, acc[1][2 * q]);
                        acc[1][2 * q + 1] = ffma2(i1, wv.y, acc[1][2 * q + 1]);
                        acc[2][2 * q]     = ffma2(i2, wv.x, acc[2][2 * q]);
                        acc[2][2 * q + 1] = ffma2(i2, wv.y, acc[2][2 * q + 1]);
                    }
                }
            }

            // L1 epilogue -> packed h1
            u64 n[3][4];
#pragma unroll
            for (int t = 0; t < 3; t++)
#pragma unroll
                for (int q = 0; q < 4; q++) {
                    float2 fa = unpack2(acc[t][2 * q]);
                    float2 fb = unpack2(acc[t][2 * q + 1]);
                    n[t][q] = pack2(clip1(fa.x + fa.y + b1f[2 * q]),
                                    clip1(fb.x + fb.y + b1f[2 * q + 1]));
                }

            // layer 2: 4 feature-pairs
            u64 a2[3][8];
#pragma unroll
            for (int t = 0; t < 3; t++)
#pragma unroll
                for (int o = 0; o < 8; o++) a2[t][o] = 0ull;
#pragma unroll
            for (int fp = 0; fp < 4; fp++) {
#pragma unroll
                for (int q = 0; q < 4; q++) {
                    ulonglong2 wv = SW2v[fp * 4 + q];
#pragma unroll
                    for (int t = 0; t < 3; t++) {
                        a2[t][2 * q]     = ffma2(n[t][fp], wv.x, a2[t][2 * q]);
                        a2[t][2 * q + 1] = ffma2(n[t][fp], wv.y, a2[t][2 * q + 1]);
                    }
                }
            }
            u64 m[3][4];
#pragma unroll
            for (int t = 0; t < 3; t++)
#pragma unroll
                for (int q = 0; q < 4; q++) {
                    float2 fa = unpack2(a2[t][2 * q]);
                    float2 fb = unpack2(a2[t][2 * q + 1]);
                    m[t][q] = pack2(clip1(fa.x + fa.y + b2f[2 * q]),
                                    clip1(fb.x + fb.y + b2f[2 * q + 1]));
                }

            // layer 3: dot8 -> v
            {
                int rr[3] = {r0, r1, r2};
                int pp[3] = {p0, p1, p2};
#pragma unroll
                for (int t = 0; t < 3; t++) {
                    u64 s = ffma2(m[t][0], w3p[0],
                            ffma2(m[t][1], w3p[1],
                            ffma2(m[t][2], w3p[2],
                            ffma2(m[t][3], w3p[3], 0ull))));
                    float2 sf = unpack2(s);
                    warp_vb[rr[t] * VSTRIDE + pp[t]] = clip1(sf.x + sf.y + b3s);
                }
            }
        }
        __syncwarp();

        // ---- head: 8 rows, lane = (oq, r) ----
        const float* vrow = warp_vb + hr * VSTRIDE;
        u64 g[4] = {0ull, 0ull, 0ull, 0ull};
#pragma unroll
        for (int fp = 0; fp < 19; fp++) {
            u64 iv = *reinterpret_cast<const u64*>(vrow + 2 * fp);
            ulonglong2 wa = E1Tv[fp * 8 + 2 * hoq];
            ulonglong2 wb = E1Tv[fp * 8 + 2 * hoq + 1];
            g[0] = ffma2(iv, wa.x, g[0]);
            g[1] = ffma2(iv, wa.y, g[1]);
            g[2] = ffma2(iv, wb.x, g[2]);
            g[3] = ffma2(iv, wb.y, g[3]);
        }
        float gv[4];
#pragma unroll
        for (int k = 0; k < 4; k++) {
            float2 f = unpack2(g[k]);
            gv[k] = clip1(f.x + f.y + c1f[k]);
        }
        u64 q0 = pack2(gv[0], gv[1]), q1 = pack2(gv[2], gv[3]);

        u64 z[8];
#pragma unroll
        for (int c = 0; c < 4; c++) {
            z[2 * c]     = shfl64(q0, c * 8 + hr);
            z[2 * c + 1] = shfl64(q1, c * 8 + hr);
        }

        u64 d[4] = {0ull, 0ull, 0ull, 0ull};
#pragma unroll
        for (int fp = 0; fp < 8; fp++) {
            ulonglong2 wa = E2Tv[fp * 8 + 2 * hoq];
            ulonglong2 wb = E2Tv[fp * 8 + 2 * hoq + 1];
            d[0] = ffma2(z[fp], wa.x, d[0]);
            d[1] = ffma2(z[fp], wa.y, d[1]);
            d[2] = ffma2(z[fp], wb.x, d[2]);
            d[3] = ffma2(z[fp], wb.y, d[3]);
        }
        float dv[4];
#pragma unroll
        for (int k = 0; k < 4; k++) {
            float2 f = unpack2(d[k]);
            dv[k] = clip1(f.x + f.y + c2f[k]);
        }
        u64 s = ffma2(pack2(dv[0], dv[1]), e3p0,
                ffma2(pack2(dv[2], dv[3]), e3p1, 0ull));
        float2 sf = unpack2(s);
        float part = sf.x + sf.y;
        part += __shfl_xor_sync(0xffffffffu, part, 8);
        part += __shfl_xor_sync(0xffffffffu, part, 16);
        int row = rb + hr;
        if (hoq == 0 && row < B) out[row] = clip1(part + c3s);
    }
}

extern "C" void kernel_launch(void* const* d_in, const int* in_sizes, int n_in,
                              void* d_out, int out_size)
{
    const float* inp = (const float*)d_in[0];
    const float* W1  = (const float*)d_in[1];
    const float* b1  = (const float*)d_in[2];
    const float* W2  = (const float*)d_in[3];
    const float* b2  = (const float*)d_in[4];
    const float* W3  = (const float*)d_in[5];
    const float* b3  = (const float*)d_in[6];
    const float* E1  = (const float*)d_in[7];
    const float* c1  = (const float*)d_in[8];
    const float* E2  = (const float*)d_in[9];
    const float* c2  = (const float*)d_in[10];
    const float* E3  = (const float*)d_in[11];
    const float* c3  = (const float*)d_in[12];

    int B = in_sizes[0] / 385;

    cudaFuncSetAttribute(lila_kernel, cudaFuncAttributeMaxDynamicSharedMemorySize,
                         (int)SMEM_BYTES);

    lila_kernel<<<296, NTHREADS, SMEM_BYTES>>>(inp, W1, b1, W2, b2, W3, b3,
                                               E1, c1, E2, c2, E3, c3,
                                               (float*)d_out, B);
}